// round 7
// baseline (speedup 1.0000x reference)
#include <cuda_runtime.h>
#include <cstdint>

typedef unsigned long long u64;

// ---------- packed dual-fp32 helpers (f32x2, native on sm_100a) ----------
__device__ __forceinline__ u64 pack2(float x, float y) {
    u64 r; asm("mov.b64 %0, {%1, %2};" : "=l"(r) : "f"(x), "f"(y)); return r;
}
__device__ __forceinline__ void unpack2(u64 v, float& x, float& y) {
    asm("mov.b64 {%0, %1}, %2;" : "=f"(x), "=f"(y) : "l"(v));
}
__device__ __forceinline__ u64 ffma2(u64 a, u64 b, u64 c) {
    u64 d; asm("fma.rn.f32x2 %0, %1, %2, %3;" : "=l"(d) : "l"(a), "l"(b), "l"(c)); return d;
}
__device__ __forceinline__ u64 mul2(u64 a, u64 b) {
    u64 d; asm("mul.rn.f32x2 %0, %1, %2;" : "=l"(d) : "l"(a), "l"(b)); return d;
}

// ---------- accurate fast transcendentals (MUFU EX2 + RCP, ~1e-7 rel) ----------
__device__ __forceinline__ float sigmoid_f(float x) {
    float e = __expf(-x);
    return __fdividef(1.0f, 1.0f + e);
}
__device__ __forceinline__ float tanh_f(float x) {
    float e = __expf(-2.0f * x);
    return __fdividef(1.0f - e, 1.0f + e);
}

// ---------- cp.async helpers ----------
__device__ __forceinline__ void cp16(uint32_t dst_smem, const float* src) {
    asm volatile("cp.async.cg.shared.global [%0], [%1], 16;" :: "r"(dst_smem), "l"(src));
}
__device__ __forceinline__ void cp_commit() { asm volatile("cp.async.commit_group;"); }
__device__ __forceinline__ void cp_wait2()  { asm volatile("cp.async.wait_group 2;"); }
__device__ __forceinline__ void cp_wait0()  { asm volatile("cp.async.wait_group 0;"); }

// Per-thread loop-invariant weights: column set {d,16+d,32+d,48+d}, k in pairs.
struct NodeConsts {
    u64 wi[12], wf[12], wc[12], wo[12];   // 96 regs
    float bi, bf, bc, bo;                 // scalar fused biases (bx+bh+b_gates)
    float wp0, wp1, wp2, wld, bl;
};

#define WPB    4            // warps per block
#define STAGES 4
#define GROUP  8            // nodes per warp-iteration (4 pairs)
// Stage float layout: x[8][8] @0, h[8][16] @64, c[8][16] @192 -> 320 floats
#define ST_X 0
#define ST_H 64
#define ST_C 192
#define ST_F 320
#define ST_BYTES (ST_F * 4)

__device__ __forceinline__ void issue_group(uint32_t sb, int lane, int n0,
                                            const float* __restrict__ x,
                                            const float* __restrict__ h,
                                            const float* __restrict__ c)
{
    const int l4 = lane * 4;
    cp16(sb + ST_H * 4 + lane * 16, h + n0 * 16 + l4);    // 8 nodes x 64B
    cp16(sb + ST_C * 4 + lane * 16, c + n0 * 16 + l4);
    if (lane < 16)
        cp16(sb + ST_X * 4 + lane * 16, x + n0 * 8 + l4); // 8 nodes x 32B
}

__global__ __launch_bounds__(128, 4)
void gconvlstm_kernel(const float* __restrict__ x,
                      const float* __restrict__ h,
                      const float* __restrict__ c,
                      const float* __restrict__ Wx, const float* __restrict__ bx,
                      const float* __restrict__ Wh, const float* __restrict__ bh,
                      const float* __restrict__ w_peep,
                      const float* __restrict__ b_gates,
                      const float* __restrict__ W_lin,
                      const float* __restrict__ b_lin,
                      float* __restrict__ out,
                      float* __restrict__ h_new,
                      float* __restrict__ c_new,
                      int N)
{
    __shared__ __align__(16) float ring[WPB][STAGES][ST_F];

    const int lane = threadIdx.x & 31;
    const int warp = threadIdx.x >> 5;
    const int s = lane >> 4;      // node slot within pair
    const int d = lane & 15;      // feature index

    // ---- one-time weight staging into registers ----
    NodeConsts K;
#pragma unroll
    for (int j = 0; j < 12; ++j) {
        const int k0 = 2 * j, k1 = k0 + 1;
        const float* r0 = (k0 < 8) ? (Wx + k0 * 64) : (Wh + (k0 - 8) * 64);
        const float* r1 = (k1 < 8) ? (Wx + k1 * 64) : (Wh + (k1 - 8) * 64);
        K.wi[j] = pack2(r0[d],      r1[d]);
        K.wf[j] = pack2(r0[16 + d], r1[16 + d]);
        K.wc[j] = pack2(r0[32 + d], r1[32 + d]);
        K.wo[j] = pack2(r0[48 + d], r1[48 + d]);
    }
    K.bi = bx[d]      + bh[d]      + b_gates[d];
    K.bf = bx[16 + d] + bh[16 + d] + b_gates[16 + d];
    K.bc = bx[32 + d] + bh[32 + d] + b_gates[32 + d];
    K.bo = bx[48 + d] + bh[48 + d] + b_gates[48 + d];
    K.wp0 = w_peep[d]; K.wp1 = w_peep[16 + d]; K.wp2 = w_peep[32 + d];
    K.wld = W_lin[d];  K.bl  = b_lin[0];

    const int ngroups = (N + GROUP - 1) / GROUP;
    const int stride  = (int)gridDim.x * WPB;
    const int g0      = (int)blockIdx.x * WPB + warp;
    if (g0 >= ngroups) return;

    const int nmax0 = (N >= GROUP) ? (N - GROUP) : 0;
    uint32_t sbase = (uint32_t)__cvta_generic_to_shared(&ring[warp][0][0]);

    // ---- prologue: fill stages 0..2 ----
#pragma unroll
    for (int st = 0; st < 3; ++st) {
        int gg = g0 + st * stride;
        int n0 = (gg < ngroups) ? gg * GROUP : nmax0;
        if (n0 > nmax0) n0 = nmax0;
        issue_group(sbase + st * ST_BYTES, lane, n0, x, h, c);
        cp_commit();
    }

    int st = 0;
    for (int g = g0; g < ngroups; g += stride) {
        cp_wait2();
        __syncwarp();

        // ---- prefetch stage st+3 ----
        {
            int gg = g + 3 * stride;
            int n0 = (gg < ngroups) ? gg * GROUP : nmax0;
            if (n0 > nmax0) n0 = nmax0;
            issue_group(sbase + ((st + 3) & 3) * ST_BYTES, lane, n0, x, h, c);
            cp_commit();
        }

        const float* S = &ring[warp][st][0];
        const int nb = g * GROUP;
        // group-base output pointers; per-pair offsets are compile-time imms
        float* cb = c_new + nb * 16 + d;
        float* hb = h_new + nb * 16 + d;
        float* ob = out + nb;
        const bool tail_ok = (nb + GROUP <= N);   // fast path: whole group valid

        // ---- consume: 4 pairs (8 nodes) ----
#pragma unroll
        for (int q = 0; q < 4; ++q) {
            const int node = 2 * q + s;
            const ulonglong2* xv = reinterpret_cast<const ulonglong2*>(S + ST_X + node * 8);
            const ulonglong2* hv = reinterpret_cast<const ulonglong2*>(S + ST_H + node * 16);
            ulonglong2 xa = xv[0], xb = xv[1];
            ulonglong2 h0 = hv[0], h1 = hv[1], h2 = hv[2], h3 = hv[3];
            const float cv = S[ST_C + node * 16 + d];

            u64 ai = mul2(xa.x, K.wi[0]);
            u64 af = mul2(xa.x, K.wf[0]);
            u64 ac = mul2(xa.x, K.wc[0]);
            u64 ao = mul2(xa.x, K.wo[0]);
#define STEP(v, j) \
            ai = ffma2(v, K.wi[j], ai); af = ffma2(v, K.wf[j], af); \
            ac = ffma2(v, K.wc[j], ac); ao = ffma2(v, K.wo[j], ao);
            STEP(xa.y, 1)  STEP(xb.x, 2)  STEP(xb.y, 3)
            STEP(h0.x, 4)  STEP(h0.y, 5)  STEP(h1.x, 6)  STEP(h1.y, 7)
            STEP(h2.x, 8)  STEP(h2.y, 9)  STEP(h3.x, 10) STEP(h3.y, 11)
#undef STEP
            float g0f, g1f, gi, gf, gc, go;
            unpack2(ai, g0f, g1f); gi = g0f + g1f + K.bi;
            unpack2(af, g0f, g1f); gf = g0f + g1f + K.bf;
            unpack2(ac, g0f, g1f); gc = g0f + g1f + K.bc;
            unpack2(ao, g0f, g1f); go = g0f + g1f + K.bo;

            const float iv = sigmoid_f(fmaf(K.wp0, cv, gi));
            const float fv = sigmoid_f(fmaf(K.wp1, cv, gf));
            const float tv = tanh_f(gc);
            const float cn = fmaf(fv, cv, iv * tv);
            const float ov = sigmoid_f(fmaf(K.wp2, cn, go));
            const float hn = ov * tanh_f(cn);

            float r = fmaxf(hn, 0.0f) * K.wld;
            r += __shfl_xor_sync(0xffffffffu, r, 1);
            r += __shfl_xor_sync(0xffffffffu, r, 2);
            r += __shfl_xor_sync(0xffffffffu, r, 4);
            r += __shfl_xor_sync(0xffffffffu, r, 8);

            if (tail_ok || (nb + node < N)) {
                cb[node * 16] = cn;              // 128B coalesced per warp
                hb[node * 16] = hn;
                if (d == 0) ob[node] = r + K.bl;
            }
        }

        __syncwarp();          // stage st free for the prefetch 3 iterations out
        st = (st + 1) & 3;
    }
    cp_wait0();
}

extern "C" void kernel_launch(void* const* d_in, const int* in_sizes, int n_in,
                              void* d_out, int out_size) {
    // metadata order: x, edge_index(unused), edge_attr(unused), h, c,
    //                 Wx, bx, Wh, bh, w_peep, b_gates, W_lin, b_lin
    const float* x  = (const float*)d_in[0];
    const float* h  = (const float*)d_in[3];
    const float* c  = (const float*)d_in[4];
    const float* Wx = (const float*)d_in[5];
    const float* bx = (const float*)d_in[6];
    const float* Wh = (const float*)d_in[7];
    const float* bh = (const float*)d_in[8];
    const float* wp = (const float*)d_in[9];
    const float* bg = (const float*)d_in[10];
    const float* wl = (const float*)d_in[11];
    const float* bl = (const float*)d_in[12];

    const int N = in_sizes[0] / 8;   // x is (N, 8)

    float* out = (float*)d_out;
    float* hn  = out + (size_t)N;
    float* cn  = hn + (size_t)N * 16;

    const int threads = 128;
    const int blocks  = 592;   // 4 resident blocks x 148 SMs, persistent
    gconvlstm_kernel<<<blocks, threads>>>(x, h, c, Wx, bx, Wh, bh, wp, bg, wl, bl,
                                          out, hn, cn, N);
}

// round 8
// speedup vs baseline: 1.1963x; 1.1963x over previous
#include <cuda_runtime.h>
#include <cstdint>

typedef unsigned long long u64;

// ---------- packed dual-fp32 helpers (f32x2, native on sm_100a) ----------
__device__ __forceinline__ u64 pack2(float x, float y) {
    u64 r; asm("mov.b64 %0, {%1, %2};" : "=l"(r) : "f"(x), "f"(y)); return r;
}
__device__ __forceinline__ void unpack2(u64 v, float& x, float& y) {
    asm("mov.b64 {%0, %1}, %2;" : "=f"(x), "=f"(y) : "l"(v));
}
__device__ __forceinline__ u64 ffma2(u64 a, u64 b, u64 c) {
    u64 d; asm("fma.rn.f32x2 %0, %1, %2, %3;" : "=l"(d) : "l"(a), "l"(b), "l"(c)); return d;
}

// ---------- accurate fast transcendentals (MUFU EX2 + RCP, ~1e-7 rel) ----------
__device__ __forceinline__ float sigmoid_f(float x) {
    float e = __expf(-x);
    return __fdividef(1.0f, 1.0f + e);
}
__device__ __forceinline__ float tanh_f(float x) {
    float e = __expf(-2.0f * x);
    return __fdividef(1.0f - e, 1.0f + e);
}

// ---------- cp.async helpers ----------
__device__ __forceinline__ void cp16(uint32_t dst_smem, const float* src) {
    asm volatile("cp.async.cg.shared.global [%0], [%1], 16;" :: "r"(dst_smem), "l"(src));
}
__device__ __forceinline__ void cp_commit() { asm volatile("cp.async.commit_group;"); }
__device__ __forceinline__ void cp_wait1()  { asm volatile("cp.async.wait_group 1;"); }
__device__ __forceinline__ void cp_wait0()  { asm volatile("cp.async.wait_group 0;"); }

// Per-thread loop-invariant weights: column set {d,16+d,32+d,48+d}, k in pairs.
struct NodeConsts {
    u64 wi[12], wf[12], wc[12], wo[12];   // 96 regs
    u64 bi2, bf2, bc2, bo2;               // (fused bias, 0) accumulator seeds
    float wp0, wp1, wp2, wld, bl;
};

#define WPB    4            // warps per block
#define STAGES 3
#define GROUP  16           // nodes per warp-iteration (8 pairs)
// Stage float layout: x[16][8] @0, h[16][16] @128, c[16][16] @384 -> 640 floats
#define ST_X 0
#define ST_H 128
#define ST_C 384
#define ST_F 640
#define ST_BYTES (ST_F * 4)

__device__ __forceinline__ void issue_group(uint32_t sb, int lane, int n0,
                                            const float* __restrict__ x,
                                            const float* __restrict__ h,
                                            const float* __restrict__ c)
{
    const int l4 = lane * 4;
    const int l16 = lane * 16;
    cp16(sb + ST_H * 4 + l16,        h + n0 * 16 + l4);        // 512B
    cp16(sb + (ST_H + 128) * 4 + l16, h + n0 * 16 + 128 + l4); // 512B
    cp16(sb + ST_C * 4 + l16,        c + n0 * 16 + l4);
    cp16(sb + (ST_C + 128) * 4 + l16, c + n0 * 16 + 128 + l4);
    cp16(sb + ST_X * 4 + l16,        x + n0 * 8 + l4);         // 512B
}

__global__ __launch_bounds__(128, 3)
void gconvlstm_kernel(const float* __restrict__ x,
                      const float* __restrict__ h,
                      const float* __restrict__ c,
                      const float* __restrict__ Wx, const float* __restrict__ bx,
                      const float* __restrict__ Wh, const float* __restrict__ bh,
                      const float* __restrict__ w_peep,
                      const float* __restrict__ b_gates,
                      const float* __restrict__ W_lin,
                      const float* __restrict__ b_lin,
                      float* __restrict__ out,
                      float* __restrict__ h_new,
                      float* __restrict__ c_new,
                      int N)
{
    __shared__ __align__(16) float ring[WPB][STAGES][ST_F];
    __shared__ __align__(16) float obuf[WPB][GROUP * 16];   // transpose buffer for out-head

    const int lane = threadIdx.x & 31;
    const int warp = threadIdx.x >> 5;
    const int s = lane >> 4;      // node slot within pair
    const int d = lane & 15;      // feature index

    // ---- one-time weight staging into registers ----
    NodeConsts K;
#pragma unroll
    for (int j = 0; j < 12; ++j) {
        const int k0 = 2 * j, k1 = k0 + 1;
        const float* r0 = (k0 < 8) ? (Wx + k0 * 64) : (Wh + (k0 - 8) * 64);
        const float* r1 = (k1 < 8) ? (Wx + k1 * 64) : (Wh + (k1 - 8) * 64);
        K.wi[j] = pack2(r0[d],      r1[d]);
        K.wf[j] = pack2(r0[16 + d], r1[16 + d]);
        K.wc[j] = pack2(r0[32 + d], r1[32 + d]);
        K.wo[j] = pack2(r0[48 + d], r1[48 + d]);
    }
    K.bi2 = pack2(bx[d]      + bh[d]      + b_gates[d],      0.0f);
    K.bf2 = pack2(bx[16 + d] + bh[16 + d] + b_gates[16 + d], 0.0f);
    K.bc2 = pack2(bx[32 + d] + bh[32 + d] + b_gates[32 + d], 0.0f);
    K.bo2 = pack2(bx[48 + d] + bh[48 + d] + b_gates[48 + d], 0.0f);
    K.wp0 = w_peep[d]; K.wp1 = w_peep[16 + d]; K.wp2 = w_peep[32 + d];
    K.wld = W_lin[d];  K.bl  = b_lin[0];

    const int ngroups = (N + GROUP - 1) / GROUP;
    const int stride  = (int)gridDim.x * WPB;
    const int g0      = (int)blockIdx.x * WPB + warp;
    if (g0 >= ngroups) return;

    const int nmax0 = (N >= GROUP) ? (N - GROUP) : 0;
    uint32_t sbase = (uint32_t)__cvta_generic_to_shared(&ring[warp][0][0]);
    float* ow = &obuf[warp][0];

    // ---- prologue: fill stages 0..1 ----
#pragma unroll
    for (int st = 0; st < 2; ++st) {
        int gg = g0 + st * stride;
        int n0 = (gg < ngroups) ? gg * GROUP : nmax0;
        if (n0 > nmax0) n0 = nmax0;
        issue_group(sbase + st * ST_BYTES, lane, n0, x, h, c);
        cp_commit();
    }

    int st = 0;
    for (int g = g0; g < ngroups; g += stride) {
        cp_wait1();
        __syncwarp();

        // ---- prefetch stage st+2 ----
        {
            int gg = g + 2 * stride;
            int n0 = (gg < ngroups) ? gg * GROUP : nmax0;
            if (n0 > nmax0) n0 = nmax0;
            int st2 = st + 2; if (st2 >= STAGES) st2 -= STAGES;
            issue_group(sbase + st2 * ST_BYTES, lane, n0, x, h, c);
            cp_commit();
        }

        const float* S = &ring[warp][st][0];
        const int nb = g * GROUP;
        float* cb = c_new + nb * 16 + d;
        float* hb = h_new + nb * 16 + d;
        const bool tail_ok = (nb + GROUP <= N);

        // ---- consume: 8 pairs (16 nodes) ----
#pragma unroll
        for (int q = 0; q < 8; ++q) {
            const int node = 2 * q + s;
            const ulonglong2* xv = reinterpret_cast<const ulonglong2*>(S + ST_X + node * 8);
            const ulonglong2* hv = reinterpret_cast<const ulonglong2*>(S + ST_H + node * 16);
            ulonglong2 xa = xv[0], xb = xv[1];
            ulonglong2 h0 = hv[0], h1 = hv[1], h2 = hv[2], h3 = hv[3];
            const float cv = S[ST_C + node * 16 + d];

            u64 ai = ffma2(xa.x, K.wi[0], K.bi2);
            u64 af = ffma2(xa.x, K.wf[0], K.bf2);
            u64 ac = ffma2(xa.x, K.wc[0], K.bc2);
            u64 ao = ffma2(xa.x, K.wo[0], K.bo2);
#define STEP(v, j) \
            ai = ffma2(v, K.wi[j], ai); af = ffma2(v, K.wf[j], af); \
            ac = ffma2(v, K.wc[j], ac); ao = ffma2(v, K.wo[j], ao);
            STEP(xa.y, 1)  STEP(xb.x, 2)  STEP(xb.y, 3)
            STEP(h0.x, 4)  STEP(h0.y, 5)  STEP(h1.x, 6)  STEP(h1.y, 7)
            STEP(h2.x, 8)  STEP(h2.y, 9)  STEP(h3.x, 10) STEP(h3.y, 11)
#undef STEP
            float g0f, g1f, gi, gf, gc, go;
            unpack2(ai, g0f, g1f); gi = g0f + g1f;
            unpack2(af, g0f, g1f); gf = g0f + g1f;
            unpack2(ac, g0f, g1f); gc = g0f + g1f;
            unpack2(ao, g0f, g1f); go = g0f + g1f;

            const float iv = sigmoid_f(fmaf(K.wp0, cv, gi));
            const float fv = sigmoid_f(fmaf(K.wp1, cv, gf));
            const float tv = tanh_f(gc);
            const float cn = fmaf(fv, cv, iv * tv);
            const float ov = sigmoid_f(fmaf(K.wp2, cn, go));
            const float hn = ov * tanh_f(cn);

            // fire-and-forget: stash relu(hn)*wld for the out-head gather pass
            ow[node * 16 + d] = fmaxf(hn, 0.0f) * K.wld;

            if (tail_ok || (nb + node < N)) {
                cb[node * 16] = cn;            // 128B coalesced per warp
                hb[node * 16] = hn;
            }
        }
        __syncwarp();

        // ---- out-head: one gather pass for all 16 nodes ----
        if (lane < GROUP) {
            const float4* r4 = reinterpret_cast<const float4*>(ow + lane * 16);
            float4 a = r4[0], b2 = r4[1], c2 = r4[2], e = r4[3];
            float r = ((a.x + a.y) + (a.z + a.w)) + ((b2.x + b2.y) + (b2.z + b2.w))
                    + ((c2.x + c2.y) + (c2.z + c2.w)) + ((e.x + e.y) + (e.z + e.w));
            const int n = nb + lane;
            if (n < N) out[n] = r + K.bl;
        }

        __syncwarp();          // stage st + obuf free for reuse
        st = st + 1; if (st >= STAGES) st = 0;
    }
    cp_wait0();
}

extern "C" void kernel_launch(void* const* d_in, const int* in_sizes, int n_in,
                              void* d_out, int out_size) {
    // metadata order: x, edge_index(unused), edge_attr(unused), h, c,
    //                 Wx, bx, Wh, bh, w_peep, b_gates, W_lin, b_lin
    const float* x  = (const float*)d_in[0];
    const float* h  = (const float*)d_in[3];
    const float* c  = (const float*)d_in[4];
    const float* Wx = (const float*)d_in[5];
    const float* bx = (const float*)d_in[6];
    const float* Wh = (const float*)d_in[7];
    const float* bh = (const float*)d_in[8];
    const float* wp = (const float*)d_in[9];
    const float* bg = (const float*)d_in[10];
    const float* wl = (const float*)d_in[11];
    const float* bl = (const float*)d_in[12];

    const int N = in_sizes[0] / 8;   // x is (N, 8)

    float* out = (float*)d_out;
    float* hn  = out + (size_t)N;
    float* cn  = hn + (size_t)N * 16;

    const int threads = 128;
    const int blocks  = 444;   // 3 resident blocks x 148 SMs, persistent
    gconvlstm_kernel<<<blocks, threads>>>(x, h, c, Wx, bx, Wh, bh, wp, bg, wl, bl,
                                          out, hn, cn, N);
}

// round 9
// speedup vs baseline: 1.4328x; 1.1978x over previous
#include <cuda_runtime.h>
#include <cstdint>

typedef unsigned long long u64;

// ---------- packed dual-fp32 helpers (f32x2, native on sm_100a) ----------
__device__ __forceinline__ u64 pack2(float x, float y) {
    u64 r; asm("mov.b64 %0, {%1, %2};" : "=l"(r) : "f"(x), "f"(y)); return r;
}
__device__ __forceinline__ void unpack2(u64 v, float& x, float& y) {
    asm("mov.b64 {%0, %1}, %2;" : "=f"(x), "=f"(y) : "l"(v));
}
__device__ __forceinline__ u64 ffma2(u64 a, u64 b, u64 c) {
    u64 d; asm("fma.rn.f32x2 %0, %1, %2, %3;" : "=l"(d) : "l"(a), "l"(b), "l"(c)); return d;
}

// ---------- hardware tanh transcendentals (single MUFU.TANH each) ----------
__device__ __forceinline__ float tanh_a(float x) {
    float r; asm("tanh.approx.f32 %0, %1;" : "=f"(r) : "f"(x)); return r;
}
__device__ __forceinline__ float sigmoid_a(float x) {
    // sigmoid(x) = 0.5*tanh(0.5x) + 0.5
    return fmaf(0.5f, tanh_a(0.5f * x), 0.5f);
}

// ---------- cp.async helpers ----------
__device__ __forceinline__ void cp16(uint32_t dst_smem, const float* src) {
    asm volatile("cp.async.cg.shared.global [%0], [%1], 16;" :: "r"(dst_smem), "l"(src));
}
__device__ __forceinline__ void cp_commit() { asm volatile("cp.async.commit_group;"); }
__device__ __forceinline__ void cp_wait1()  { asm volatile("cp.async.wait_group 1;"); }
__device__ __forceinline__ void cp_wait0()  { asm volatile("cp.async.wait_group 0;"); }

// Per-thread loop-invariant weights: column set {d,16+d,32+d,48+d}, k in pairs.
struct NodeConsts {
    u64 wi[12], wf[12], wc[12], wo[12];   // 96 regs
    u64 bi2, bf2, bc2, bo2;               // (fused bias, 0) accumulator seeds
    float wp0, wp1, wp2, wld, bl;
};

#define WPB    4            // warps per block
#define STAGES 3
#define GROUP  16           // nodes per warp-iteration (8 pairs)
// Stage float layout: x[16][8] @0, h[16][16] @128, c[16][16] @384 -> 640 floats
#define ST_X 0
#define ST_H 128
#define ST_C 384
#define ST_F 640
#define ST_BYTES (ST_F * 4)

__device__ __forceinline__ void issue_group(uint32_t sb, int lane, int n0,
                                            const float* __restrict__ x,
                                            const float* __restrict__ h,
                                            const float* __restrict__ c)
{
    const int l4 = lane * 4;
    const int l16 = lane * 16;
    cp16(sb + ST_H * 4 + l16,         h + n0 * 16 + l4);
    cp16(sb + (ST_H + 128) * 4 + l16, h + n0 * 16 + 128 + l4);
    cp16(sb + ST_C * 4 + l16,         c + n0 * 16 + l4);
    cp16(sb + (ST_C + 128) * 4 + l16, c + n0 * 16 + 128 + l4);
    cp16(sb + ST_X * 4 + l16,         x + n0 * 8 + l4);
}

__global__ __launch_bounds__(128, 3)
void gconvlstm_kernel(const float* __restrict__ x,
                      const float* __restrict__ h,
                      const float* __restrict__ c,
                      const float* __restrict__ Wx, const float* __restrict__ bx,
                      const float* __restrict__ Wh, const float* __restrict__ bh,
                      const float* __restrict__ w_peep,
                      const float* __restrict__ b_gates,
                      const float* __restrict__ W_lin,
                      const float* __restrict__ b_lin,
                      float* __restrict__ out,
                      float* __restrict__ h_new,
                      float* __restrict__ c_new,
                      int N)
{
    __shared__ __align__(16) float ring[WPB][STAGES][ST_F];
    __shared__ __align__(16) float obuf[WPB][GROUP * 16];   // transpose buffer for out-head

    const int lane = threadIdx.x & 31;
    const int warp = threadIdx.x >> 5;
    const int s = lane >> 4;      // node slot within pair
    const int d = lane & 15;      // feature index

    // ---- one-time weight staging into registers ----
    NodeConsts K;
#pragma unroll
    for (int j = 0; j < 12; ++j) {
        const int k0 = 2 * j, k1 = k0 + 1;
        const float* r0 = (k0 < 8) ? (Wx + k0 * 64) : (Wh + (k0 - 8) * 64);
        const float* r1 = (k1 < 8) ? (Wx + k1 * 64) : (Wh + (k1 - 8) * 64);
        K.wi[j] = pack2(r0[d],      r1[d]);
        K.wf[j] = pack2(r0[16 + d], r1[16 + d]);
        K.wc[j] = pack2(r0[32 + d], r1[32 + d]);
        K.wo[j] = pack2(r0[48 + d], r1[48 + d]);
    }
    K.bi2 = pack2(bx[d]      + bh[d]      + b_gates[d],      0.0f);
    K.bf2 = pack2(bx[16 + d] + bh[16 + d] + b_gates[16 + d], 0.0f);
    K.bc2 = pack2(bx[32 + d] + bh[32 + d] + b_gates[32 + d], 0.0f);
    K.bo2 = pack2(bx[48 + d] + bh[48 + d] + b_gates[48 + d], 0.0f);
    K.wp0 = w_peep[d]; K.wp1 = w_peep[16 + d]; K.wp2 = w_peep[32 + d];
    K.wld = W_lin[d];  K.bl  = b_lin[0];

    const int ngroups = (N + GROUP - 1) / GROUP;
    const int stride  = (int)gridDim.x * WPB;
    const int g0      = (int)blockIdx.x * WPB + warp;
    if (g0 >= ngroups) return;

    const int nmax0 = (N >= GROUP) ? (N - GROUP) : 0;
    uint32_t sbase = (uint32_t)__cvta_generic_to_shared(&ring[warp][0][0]);
    float* ow = &obuf[warp][0];

    // ---- prologue: fill stages 0..1 ----
#pragma unroll
    for (int st = 0; st < 2; ++st) {
        int gg = g0 + st * stride;
        int n0 = (gg < ngroups) ? gg * GROUP : nmax0;
        if (n0 > nmax0) n0 = nmax0;
        issue_group(sbase + st * ST_BYTES, lane, n0, x, h, c);
        cp_commit();
    }

    int st = 0;
    for (int g = g0; g < ngroups; g += stride) {
        cp_wait1();
        __syncwarp();

        // ---- prefetch stage st+2 ----
        {
            int gg = g + 2 * stride;
            int n0 = (gg < ngroups) ? gg * GROUP : nmax0;
            if (n0 > nmax0) n0 = nmax0;
            int st2 = st + 2; if (st2 >= STAGES) st2 -= STAGES;
            issue_group(sbase + st2 * ST_BYTES, lane, n0, x, h, c);
            cp_commit();
        }

        const float* S = &ring[warp][st][0];
        const int nb = g * GROUP;
        float* cb = c_new + nb * 16 + d;
        float* hb = h_new + nb * 16 + d;
        const bool tail_ok = (nb + GROUP <= N);

        // ---- consume: 8 pairs (16 nodes) ----
#pragma unroll
        for (int q = 0; q < 8; ++q) {
            const int node = 2 * q + s;
            const ulonglong2* xv = reinterpret_cast<const ulonglong2*>(S + ST_X + node * 8);
            const ulonglong2* hv = reinterpret_cast<const ulonglong2*>(S + ST_H + node * 16);
            ulonglong2 xa = xv[0], xb = xv[1];
            ulonglong2 h0 = hv[0], h1 = hv[1], h2 = hv[2], h3 = hv[3];
            const float cv = S[ST_C + node * 16 + d];

            u64 ai = ffma2(xa.x, K.wi[0], K.bi2);
            u64 af = ffma2(xa.x, K.wf[0], K.bf2);
            u64 ac = ffma2(xa.x, K.wc[0], K.bc2);
            u64 ao = ffma2(xa.x, K.wo[0], K.bo2);
#define STEP(v, j) \
            ai = ffma2(v, K.wi[j], ai); af = ffma2(v, K.wf[j], af); \
            ac = ffma2(v, K.wc[j], ac); ao = ffma2(v, K.wo[j], ao);
            STEP(xa.y, 1)  STEP(xb.x, 2)  STEP(xb.y, 3)
            STEP(h0.x, 4)  STEP(h0.y, 5)  STEP(h1.x, 6)  STEP(h1.y, 7)
            STEP(h2.x, 8)  STEP(h2.y, 9)  STEP(h3.x, 10) STEP(h3.y, 11)
#undef STEP
            float g0f, g1f, gi, gf, gc, go;
            unpack2(ai, g0f, g1f); gi = g0f + g1f;
            unpack2(af, g0f, g1f); gf = g0f + g1f;
            unpack2(ac, g0f, g1f); gc = g0f + g1f;
            unpack2(ao, g0f, g1f); go = g0f + g1f;

            const float iv = sigmoid_a(fmaf(K.wp0, cv, gi));
            const float fv = sigmoid_a(fmaf(K.wp1, cv, gf));
            const float tv = tanh_a(gc);
            const float cn = fmaf(fv, cv, iv * tv);
            const float ov = sigmoid_a(fmaf(K.wp2, cn, go));
            const float hn = ov * tanh_a(cn);

            // fire-and-forget: stash relu(hn)*wld for the out-head gather pass
            ow[node * 16 + d] = fmaxf(hn, 0.0f) * K.wld;

            if (tail_ok || (nb + node < N)) {
                cb[node * 16] = cn;            // 128B coalesced per warp
                hb[node * 16] = hn;
            }
        }
        __syncwarp();

        // ---- out-head: one gather pass for all 16 nodes ----
        if (lane < GROUP) {
            const float4* r4 = reinterpret_cast<const float4*>(ow + lane * 16);
            float4 a = r4[0], b2 = r4[1], c2 = r4[2], e = r4[3];
            float r = ((a.x + a.y) + (a.z + a.w)) + ((b2.x + b2.y) + (b2.z + b2.w))
                    + ((c2.x + c2.y) + (c2.z + c2.w)) + ((e.x + e.y) + (e.z + e.w));
            const int n = nb + lane;
            if (n < N) out[n] = r + K.bl;
        }

        __syncwarp();          // stage st + obuf free for reuse
        st = st + 1; if (st >= STAGES) st = 0;
    }
    cp_wait0();
}

extern "C" void kernel_launch(void* const* d_in, const int* in_sizes, int n_in,
                              void* d_out, int out_size) {
    // metadata order: x, edge_index(unused), edge_attr(unused), h, c,
    //                 Wx, bx, Wh, bh, w_peep, b_gates, W_lin, b_lin
    const float* x  = (const float*)d_in[0];
    const float* h  = (const float*)d_in[3];
    const float* c  = (const float*)d_in[4];
    const float* Wx = (const float*)d_in[5];
    const float* bx = (const float*)d_in[6];
    const float* Wh = (const float*)d_in[7];
    const float* bh = (const float*)d_in[8];
    const float* wp = (const float*)d_in[9];
    const float* bg = (const float*)d_in[10];
    const float* wl = (const float*)d_in[11];
    const float* bl = (const float*)d_in[12];

    const int N = in_sizes[0] / 8;   // x is (N, 8)

    float* out = (float*)d_out;
    float* hn  = out + (size_t)N;
    float* cn  = hn + (size_t)N * 16;

    const int threads = 128;
    const int blocks  = 444;   // 3 resident blocks x 148 SMs, persistent
    gconvlstm_kernel<<<blocks, threads>>>(x, h, c, Wx, bx, Wh, bh, wp, bg, wl, bl,
                                          out, hn, cn, N);
}

// round 10
// speedup vs baseline: 1.4703x; 1.0262x over previous
#include <cuda_runtime.h>
#include <cstdint>

typedef unsigned long long u64;

// ---------- packed dual-fp32 helpers (f32x2, native on sm_100a) ----------
__device__ __forceinline__ u64 pack2(float x, float y) {
    u64 r; asm("mov.b64 %0, {%1, %2};" : "=l"(r) : "f"(x), "f"(y)); return r;
}
__device__ __forceinline__ void unpack2(u64 v, float& x, float& y) {
    asm("mov.b64 {%0, %1}, %2;" : "=f"(x), "=f"(y) : "l"(v));
}
__device__ __forceinline__ u64 ffma2(u64 a, u64 b, u64 c) {
    u64 d; asm("fma.rn.f32x2 %0, %1, %2, %3;" : "=l"(d) : "l"(a), "l"(b), "l"(c)); return d;
}

// ---------- hardware tanh (single MUFU.TANH) ----------
__device__ __forceinline__ float tanh_a(float x) {
    float r; asm("tanh.approx.f32 %0, %1;" : "=f"(r) : "f"(x)); return r;
}
// sigmoid(x) = 0.5*tanh(0.5x)+0.5 ; the 0.5*x is pre-folded into weights/biases.

// ---------- cp.async helpers ----------
__device__ __forceinline__ void cp16(uint32_t dst_smem, const float* src) {
    asm volatile("cp.async.cg.shared.global [%0], [%1], 16;" :: "r"(dst_smem), "l"(src));
}
__device__ __forceinline__ void cp_commit() { asm volatile("cp.async.commit_group;"); }
__device__ __forceinline__ void cp_wait1()  { asm volatile("cp.async.wait_group 1;"); }
__device__ __forceinline__ void cp_wait0()  { asm volatile("cp.async.wait_group 0;"); }

// Per-thread loop-invariant weights: column set {d,16+d,32+d,48+d}, k in pairs.
// i/f/o gate weights, biases and peepholes are PRESCALED by 0.5 (sigmoid fold).
struct NodeConsts {
    u64 wi[12], wf[12], wc[12], wo[12];   // 96 regs
    u64 bi2, bf2, bc2, bo2;               // (fused bias, 0) accumulator seeds
    float wp0, wp1, wp2, wld, bl;
};

#define WPB    4            // warps per block
#define STAGES 3
#define GROUP  16           // nodes per warp-iteration (8 pairs)
// Stage float layout: x[16][8] @0, h[16][16] @128, c[16][16] @384 -> 640 floats
#define ST_X 0
#define ST_H 128
#define ST_C 384
#define ST_F 640
#define ST_BYTES (ST_F * 4)

__device__ __forceinline__ void issue_group(uint32_t sb, int lane, int n0,
                                            const float* __restrict__ x,
                                            const float* __restrict__ h,
                                            const float* __restrict__ c)
{
    const int l4 = lane * 4;
    const int l16 = lane * 16;
    cp16(sb + ST_H * 4 + l16,         h + n0 * 16 + l4);
    cp16(sb + (ST_H + 128) * 4 + l16, h + n0 * 16 + 128 + l4);
    cp16(sb + ST_C * 4 + l16,         c + n0 * 16 + l4);
    cp16(sb + (ST_C + 128) * 4 + l16, c + n0 * 16 + 128 + l4);
    cp16(sb + ST_X * 4 + l16,         x + n0 * 8 + l4);
}

// Accumulator set for one pair-slot (this thread's node within the pair).
struct P4 { u64 ai, af, ac, ao; float cv; };

__device__ __forceinline__ P4 gemv_pair(const NodeConsts& K, const float* S,
                                        int node, int d)
{
    const ulonglong2* xv = reinterpret_cast<const ulonglong2*>(S + ST_X + node * 8);
    const ulonglong2* hv = reinterpret_cast<const ulonglong2*>(S + ST_H + node * 16);
    ulonglong2 xa = xv[0], xb = xv[1];
    ulonglong2 h0 = hv[0], h1 = hv[1], h2 = hv[2], h3 = hv[3];
    P4 r;
    r.cv = S[ST_C + node * 16 + d];
    r.ai = ffma2(xa.x, K.wi[0], K.bi2);
    r.af = ffma2(xa.x, K.wf[0], K.bf2);
    r.ac = ffma2(xa.x, K.wc[0], K.bc2);
    r.ao = ffma2(xa.x, K.wo[0], K.bo2);
#define STEP(v, j) \
    r.ai = ffma2(v, K.wi[j], r.ai); r.af = ffma2(v, K.wf[j], r.af); \
    r.ac = ffma2(v, K.wc[j], r.ac); r.ao = ffma2(v, K.wo[j], r.ao);
    STEP(xa.y, 1)  STEP(xb.x, 2)  STEP(xb.y, 3)
    STEP(h0.x, 4)  STEP(h0.y, 5)  STEP(h1.x, 6)  STEP(h1.y, 7)
    STEP(h2.x, 8)  STEP(h2.y, 9)  STEP(h3.x, 10) STEP(h3.y, 11)
#undef STEP
    return r;
}

__device__ __forceinline__ void gates_pair(const NodeConsts& K, const P4& A,
                                           int node, int d, bool valid,
                                           float* __restrict__ cb,
                                           float* __restrict__ hb,
                                           float* __restrict__ ow)
{
    float g0f, g1f, gi, gf, gc, go;
    unpack2(A.ai, g0f, g1f); gi = g0f + g1f;     // prescaled by 0.5
    unpack2(A.af, g0f, g1f); gf = g0f + g1f;     // prescaled by 0.5
    unpack2(A.ac, g0f, g1f); gc = g0f + g1f;     // unscaled (tanh gate)
    unpack2(A.ao, g0f, g1f); go = g0f + g1f;     // prescaled by 0.5

    const float cv = A.cv;
    const float iv = fmaf(0.5f, tanh_a(fmaf(K.wp0, cv, gi)), 0.5f);
    const float fv = fmaf(0.5f, tanh_a(fmaf(K.wp1, cv, gf)), 0.5f);
    const float tv = tanh_a(gc);
    const float cn = fmaf(fv, cv, iv * tv);
    const float ov = fmaf(0.5f, tanh_a(fmaf(K.wp2, cn, go)), 0.5f);
    const float hn = ov * tanh_a(cn);

    ow[node * 16 + d] = fmaxf(hn, 0.0f) * K.wld;   // out-head stash
    if (valid) {
        cb[node * 16] = cn;                        // 128B coalesced per warp
        hb[node * 16] = hn;
    }
}

__global__ __launch_bounds__(128, 3)
void gconvlstm_kernel(const float* __restrict__ x,
                      const float* __restrict__ h,
                      const float* __restrict__ c,
                      const float* __restrict__ Wx, const float* __restrict__ bx,
                      const float* __restrict__ Wh, const float* __restrict__ bh,
                      const float* __restrict__ w_peep,
                      const float* __restrict__ b_gates,
                      const float* __restrict__ W_lin,
                      const float* __restrict__ b_lin,
                      float* __restrict__ out,
                      float* __restrict__ h_new,
                      float* __restrict__ c_new,
                      int N)
{
    __shared__ __align__(16) float ring[WPB][STAGES][ST_F];
    __shared__ __align__(16) float obuf[WPB][GROUP * 16];

    const int lane = threadIdx.x & 31;
    const int warp = threadIdx.x >> 5;
    const int s = lane >> 4;      // node slot within pair
    const int d = lane & 15;      // feature index

    // ---- one-time weight staging; sigmoid 0.5-fold into i/f/o weights ----
    NodeConsts K;
#pragma unroll
    for (int j = 0; j < 12; ++j) {
        const int k0 = 2 * j, k1 = k0 + 1;
        const float* r0 = (k0 < 8) ? (Wx + k0 * 64) : (Wh + (k0 - 8) * 64);
        const float* r1 = (k1 < 8) ? (Wx + k1 * 64) : (Wh + (k1 - 8) * 64);
        K.wi[j] = pack2(0.5f * r0[d],      0.5f * r1[d]);
        K.wf[j] = pack2(0.5f * r0[16 + d], 0.5f * r1[16 + d]);
        K.wc[j] = pack2(r0[32 + d],        r1[32 + d]);
        K.wo[j] = pack2(0.5f * r0[48 + d], 0.5f * r1[48 + d]);
    }
    K.bi2 = pack2(0.5f * (bx[d]      + bh[d]      + b_gates[d]),      0.0f);
    K.bf2 = pack2(0.5f * (bx[16 + d] + bh[16 + d] + b_gates[16 + d]), 0.0f);
    K.bc2 = pack2(        bx[32 + d] + bh[32 + d] + b_gates[32 + d],  0.0f);
    K.bo2 = pack2(0.5f * (bx[48 + d] + bh[48 + d] + b_gates[48 + d]), 0.0f);
    K.wp0 = 0.5f * w_peep[d];
    K.wp1 = 0.5f * w_peep[16 + d];
    K.wp2 = 0.5f * w_peep[32 + d];
    K.wld = W_lin[d];  K.bl = b_lin[0];

    const int ngroups = (N + GROUP - 1) / GROUP;
    const int stride  = (int)gridDim.x * WPB;
    const int g0      = (int)blockIdx.x * WPB + warp;
    if (g0 >= ngroups) return;

    const int nmax0 = (N >= GROUP) ? (N - GROUP) : 0;
    uint32_t sbase = (uint32_t)__cvta_generic_to_shared(&ring[warp][0][0]);
    float* ow = &obuf[warp][0];

    // ---- prologue: fill stages 0..1 ----
#pragma unroll
    for (int st = 0; st < 2; ++st) {
        int gg = g0 + st * stride;
        int n0 = (gg < ngroups) ? gg * GROUP : nmax0;
        if (n0 > nmax0) n0 = nmax0;
        issue_group(sbase + st * ST_BYTES, lane, n0, x, h, c);
        cp_commit();
    }

    int st = 0;
    for (int g = g0; g < ngroups; g += stride) {
        cp_wait1();
        __syncwarp();

        // ---- prefetch stage st+2 ----
        {
            int gg = g + 2 * stride;
            int n0 = (gg < ngroups) ? gg * GROUP : nmax0;
            if (n0 > nmax0) n0 = nmax0;
            int st2 = st + 2; if (st2 >= STAGES) st2 -= STAGES;
            issue_group(sbase + st2 * ST_BYTES, lane, n0, x, h, c);
            cp_commit();
        }

        const float* S = &ring[warp][st][0];
        const int nb = g * GROUP;
        float* cb = c_new + nb * 16 + d;
        float* hb = h_new + nb * 16 + d;
        const bool tail_ok = (nb + GROUP <= N);

        // ---- consume: 8 pairs, 2-deep software pipeline ----
        // gemv(q+1) is forced between gemv(q)'s accumulators and gates(q)'s
        // MUFU tail, so fma issue of the next pair hides this pair's tail.
        P4 A = gemv_pair(K, S, s, d);          // pair 0: node = 0*2+s
#pragma unroll
        for (int q = 0; q < 8; ++q) {
            const int node = 2 * q + s;
            P4 B;
            if (q < 7) B = gemv_pair(K, S, node + 2, d);
            gates_pair(K, A, node, d, tail_ok || (nb + node < N), cb, hb, ow);
            A = B;
        }
        __syncwarp();

        // ---- out-head: one gather pass for all 16 nodes ----
        if (lane < GROUP) {
            const float4* r4 = reinterpret_cast<const float4*>(ow + lane * 16);
            float4 a = r4[0], b2 = r4[1], c2 = r4[2], e = r4[3];
            float r = ((a.x + a.y) + (a.z + a.w)) + ((b2.x + b2.y) + (b2.z + b2.w))
                    + ((c2.x + c2.y) + (c2.z + c2.w)) + ((e.x + e.y) + (e.z + e.w));
            const int n = nb + lane;
            if (n < N) out[n] = r + K.bl;
        }

        __syncwarp();
        st = st + 1; if (st >= STAGES) st = 0;
    }
    cp_wait0();
}

extern "C" void kernel_launch(void* const* d_in, const int* in_sizes, int n_in,
                              void* d_out, int out_size) {
    // metadata order: x, edge_index(unused), edge_attr(unused), h, c,
    //                 Wx, bx, Wh, bh, w_peep, b_gates, W_lin, b_lin
    const float* x  = (const float*)d_in[0];
    const float* h  = (const float*)d_in[3];
    const float* c  = (const float*)d_in[4];
    const float* Wx = (const float*)d_in[5];
    const float* bx = (const float*)d_in[6];
    const float* Wh = (const float*)d_in[7];
    const float* bh = (const float*)d_in[8];
    const float* wp = (const float*)d_in[9];
    const float* bg = (const float*)d_in[10];
    const float* wl = (const float*)d_in[11];
    const float* bl = (const float*)d_in[12];

    const int N = in_sizes[0] / 8;   // x is (N, 8)

    float* out = (float*)d_out;
    float* hn  = out + (size_t)N;
    float* cn  = hn + (size_t)N * 16;

    const int threads = 128;
    const int blocks  = 444;   // 3 resident blocks x 148 SMs, persistent
    gconvlstm_kernel<<<blocks, threads>>>(x, h, c, Wx, bx, Wh, bh, wp, bg, wl, bl,
                                          out, hn, cn, N);
}

// round 13
// speedup vs baseline: 2.4935x; 1.6959x over previous
#include <cuda_runtime.h>
#include <cstdint>

typedef unsigned int u32;

// ---------- MUFU.TANH ----------
__device__ __forceinline__ float tanh_a(float x) {
    float r; asm("tanh.approx.f32 %0, %1;" : "=f"(r) : "f"(x)); return r;
}
// pack bf16x2: lo half = first arg, hi half = second arg
__device__ __forceinline__ u32 bfpair(float lo, float hi) {
    u32 r; asm("cvt.rn.bf16x2.f32 %0, %1, %2;" : "=r"(r) : "f"(hi), "f"(lo)); return r;
}
// fp32 pair -> bf16x2 hi + bf16x2 lo (residual)
__device__ __forceinline__ void split2(float a0, float a1, u32& ph, u32& pl) {
    ph = bfpair(a0, a1);
    float h0 = __uint_as_float(ph << 16);
    float h1 = __uint_as_float(ph & 0xFFFF0000u);
    pl = bfpair(a0 - h0, a1 - h1);
}

// ---------- warp MMA: D(16x8) += A(16x16,bf16,row) * B(16x8,bf16,col) ----------
__device__ __forceinline__ void mma16816(float* d, const u32* a, const u32* b,
                                         const float* c) {
    asm("mma.sync.aligned.m16n8k16.row.col.f32.bf16.bf16.f32 "
        "{%0,%1,%2,%3}, {%4,%5,%6,%7}, {%8,%9}, {%10,%11,%12,%13};"
        : "=f"(d[0]), "=f"(d[1]), "=f"(d[2]), "=f"(d[3])
        : "r"(a[0]), "r"(a[1]), "r"(a[2]), "r"(a[3]),
          "r"(b[0]), "r"(b[1]),
          "f"(c[0]), "f"(c[1]), "f"(c[2]), "f"(c[3]));
}

// ---------- cp.async ----------
__device__ __forceinline__ void cp16(u32 dst, const float* src) {
    asm volatile("cp.async.cg.shared.global [%0], [%1], 16;" :: "r"(dst), "l"(src));
}
__device__ __forceinline__ void cp_commit() { asm volatile("cp.async.commit_group;"); }
__device__ __forceinline__ void cp_wait1()  { asm volatile("cp.async.wait_group 1;"); }
__device__ __forceinline__ void cp_wait0()  { asm volatile("cp.async.wait_group 0;"); }

#define WPB    4
#define STAGES 3
#define GROUP  16
// stage float layout: x[16][8] @0, h[16][16] @128, c[16][16] @384
#define ST_X 0
#define ST_H 128
#define ST_C 384
#define ST_F 640
#define ST_BYTES (ST_F * 4)

__device__ __forceinline__ void issue_group(u32 sb, int lane, int n0,
                                            const float* __restrict__ x,
                                            const float* __restrict__ h,
                                            const float* __restrict__ c)
{
    const int l4 = lane * 4;
    const int l16 = lane * 16;
    cp16(sb + ST_H * 4 + l16,         h + n0 * 16 + l4);
    cp16(sb + (ST_H + 128) * 4 + l16, h + n0 * 16 + 128 + l4);
    cp16(sb + ST_C * 4 + l16,         c + n0 * 16 + l4);
    cp16(sb + (ST_C + 128) * 4 + l16, c + n0 * 16 + 128 + l4);
    cp16(sb + ST_X * 4 + l16,         x + n0 * 8 + l4);
}

__global__ __launch_bounds__(128, 3)
void gconvlstm_mma(const float* __restrict__ x,
                   const float* __restrict__ h,
                   const float* __restrict__ c,
                   const float* __restrict__ Wx, const float* __restrict__ bx,
                   const float* __restrict__ Wh, const float* __restrict__ bh,
                   const float* __restrict__ wp, const float* __restrict__ bg,
                   const float* __restrict__ wl, const float* __restrict__ blin,
                   float* __restrict__ out,
                   float* __restrict__ h_new,
                   float* __restrict__ c_new,
                   int N)
{
    __shared__ __align__(16) float ring[WPB][STAGES][ST_F];   // 30720 B
    __shared__ __align__(16) float wbuf[32][64];              // 8192 B (rows 25-31 = 0)
    __shared__ __align__(16) float4 epi[16];                  // {0.5wp0,0.5wp1,0.5wp2,wld}
    __shared__ float sbl;

    const int tid  = threadIdx.x;
    const int lane = tid & 31;
    const int warp = tid >> 5;
    const int m    = lane & 3;     // threadID_in_group
    const int r0   = lane >> 2;    // groupID = fragment row

    // ---- stage full weight matrix (prescaled, bias row k=24) into smem ----
    for (int i = tid; i < 32 * 64; i += 128) {
        int k = i >> 6, n = i & 63;
        float v = 0.0f;
        if (k < 8)        v = Wx[k * 64 + n];
        else if (k < 24)  v = Wh[(k - 8) * 64 + n];
        else if (k == 24) v = bx[n] + bh[n] + bg[n];
        if (n < 32 || n >= 48) v *= 0.5f;      // sigmoid 0.5-fold (c-gate cols 32-47 unscaled)
        wbuf[k][n] = v;
    }
    if (tid < 16)
        epi[tid] = make_float4(0.5f * wp[tid], 0.5f * wp[16 + tid],
                               0.5f * wp[32 + tid], wl[tid]);
    if (tid == 0) sbl = blin[0];
    __syncthreads();

    // ---- build persistent B fragments (hi/lo): Bh/Bl[ntile j][kstep s][breg] ----
    u32 Bh[8][2][2], Bl[8][2][2];
#pragma unroll
    for (int j = 0; j < 8; ++j) {
        const int n = 8 * j + r0;              // fragment col = groupID
#pragma unroll
        for (int s = 0; s < 2; ++s)
#pragma unroll
            for (int br = 0; br < 2; ++br) {
                const int kk = s * 16 + br * 8 + 2 * m;
                split2(wbuf[kk][n], wbuf[kk + 1][n], Bh[j][s][br], Bl[j][s][br]);
            }
    }
    // per-thread epi quads for d = {2m, 2m+1, 8+2m, 9+2m}
    float4 wq0 = epi[2 * m],     wq1 = epi[2 * m + 1];
    float4 wq2 = epi[8 + 2 * m], wq3 = epi[9 + 2 * m];
    const float bl = sbl;

    const int ngroups = (N + GROUP - 1) / GROUP;
    const int stride  = (int)gridDim.x * WPB;
    const int g0      = (int)blockIdx.x * WPB + warp;
    if (g0 >= ngroups) return;

    const int nmax0 = (N >= GROUP) ? (N - GROUP) : 0;
    u32 sbase = (u32)__cvta_generic_to_shared(&ring[warp][0][0]);

    // ---- prologue: fill stages 0..1 ----
#pragma unroll
    for (int st = 0; st < 2; ++st) {
        int gg = g0 + st * stride;
        int n0 = (gg < ngroups) ? gg * GROUP : nmax0;
        if (n0 > nmax0) n0 = nmax0;
        issue_group(sbase + st * ST_BYTES, lane, n0, x, h, c);
        cp_commit();
    }

    int st = 0;
    for (int g = g0; g < ngroups; g += stride) {
        cp_wait1();
        __syncwarp();

        // prefetch stage st+2
        {
            int gg = g + 2 * stride;
            int n0 = (gg < ngroups) ? gg * GROUP : nmax0;
            if (n0 > nmax0) n0 = nmax0;
            int st2 = st + 2; if (st2 >= STAGES) st2 -= STAGES;
            issue_group(sbase + st2 * ST_BYTES, lane, n0, x, h, c);
            cp_commit();
        }

        const float* S = &ring[warp][st][0];
        const int nb = g * GROUP;

        // ---- build A fragments (rows r0, r0+8), K=32 with bias col 24 ----
        // a0/a1: k-lo (rows r0, r0+8); a2/a3: k-hi
        u32 Ah[2][4], Al[2][4];
#pragma unroll
        for (int ri = 0; ri < 2; ++ri) {
            const int row = r0 + 8 * ri;
            float2 xp = *(const float2*)(S + ST_X + row * 8 + 2 * m);       // k 0-7 pair
            float2 h1 = *(const float2*)(S + ST_H + row * 16 + 2 * m);      // k 8-15 pair
            float2 h2 = *(const float2*)(S + ST_H + row * 16 + 8 + 2 * m);  // k 16-23 pair
            split2(xp.x, xp.y, Ah[0][0 + ri], Al[0][0 + ri]);
            split2(h1.x, h1.y, Ah[0][2 + ri], Al[0][2 + ri]);
            split2(h2.x, h2.y, Ah[1][0 + ri], Al[1][0 + ri]);
            Ah[1][2 + ri] = (m == 0) ? 0x00003F80u : 0u;   // bias col: bf16(1.0) in k=24
            Al[1][2 + ri] = 0u;
        }

        // ---- MMA: D = Ah*Bh + Ah*Bl + Al*Bh  (8 independent n-tiles) ----
        float acc[8][4];
        const float zero4[4] = {0.0f, 0.0f, 0.0f, 0.0f};
#pragma unroll
        for (int j = 0; j < 8; ++j) {
            mma16816(acc[j], Ah[0], Bh[j][0], zero4);
            mma16816(acc[j], Ah[1], Bh[j][1], acc[j]);
            mma16816(acc[j], Ah[0], Bl[j][0], acc[j]);
            mma16816(acc[j], Ah[1], Bl[j][1], acc[j]);
            mma16816(acc[j], Al[0], Bh[j][0], acc[j]);
            mma16816(acc[j], Al[1], Bh[j][1], acc[j]);
        }

        // ---- epilogue: 2 rows x 4 features per thread ----
#pragma unroll
        for (int ri = 0; ri < 2; ++ri) {
            const int row = r0 + 8 * ri;
            const int n = nb + row;
            float2 ca = *(const float2*)(S + ST_C + row * 16 + 2 * m);
            float2 cb = *(const float2*)(S + ST_C + row * 16 + 8 + 2 * m);
            const float cv[4] = {ca.x, ca.y, cb.x, cb.y};

            float hn[4], cn[4], racc = 0.0f;
#pragma unroll
            for (int di = 0; di < 4; ++di) {
                const int jb = di >> 1;
                const int ci = ri * 2 + (di & 1);
                const float gi = acc[jb][ci];
                const float gf = acc[jb + 2][ci];
                const float gc = acc[jb + 4][ci];
                const float go = acc[jb + 6][ci];
                const float4 w = (di == 0) ? wq0 : (di == 1) ? wq1 : (di == 2) ? wq2 : wq3;
                const float iv = fmaf(0.5f, tanh_a(fmaf(w.x, cv[di], gi)), 0.5f);
                const float fv = fmaf(0.5f, tanh_a(fmaf(w.y, cv[di], gf)), 0.5f);
                const float tv = tanh_a(gc);
                const float cnv = fmaf(fv, cv[di], iv * tv);
                const float ov = fmaf(0.5f, tanh_a(fmaf(w.z, cnv, go)), 0.5f);
                const float hnv = ov * tanh_a(cnv);
                cn[di] = cnv; hn[di] = hnv;
                racc = fmaf(fmaxf(hnv, 0.0f), w.w, racc);
            }
            // quad reduction (threads 4r..4r+3 cover all 16 features)
            racc += __shfl_xor_sync(0xffffffffu, racc, 1);
            racc += __shfl_xor_sync(0xffffffffu, racc, 2);

            if (n < N) {
                float2* cp2 = (float2*)(c_new + (size_t)n * 16 + 2 * m);
                float2* hp2 = (float2*)(h_new + (size_t)n * 16 + 2 * m);
                cp2[0] = make_float2(cn[0], cn[1]);
                cp2[4] = make_float2(cn[2], cn[3]);     // +8 floats = 4 float2
                hp2[0] = make_float2(hn[0], hn[1]);
                hp2[4] = make_float2(hn[2], hn[3]);
                if (m == 0) out[n] = racc + bl;
            }
        }

        __syncwarp();
        st = st + 1; if (st >= STAGES) st = 0;
    }
    cp_wait0();
}

extern "C" void kernel_launch(void* const* d_in, const int* in_sizes, int n_in,
                              void* d_out, int out_size) {
    // metadata order: x, edge_index(unused), edge_attr(unused), h, c,
    //                 Wx, bx, Wh, bh, w_peep, b_gates, W_lin, b_lin
    const float* x  = (const float*)d_in[0];
    const float* h  = (const float*)d_in[3];
    const float* c  = (const float*)d_in[4];
    const float* Wx = (const float*)d_in[5];
    const float* bx = (const float*)d_in[6];
    const float* Wh = (const float*)d_in[7];
    const float* bh = (const float*)d_in[8];
    const float* wp = (const float*)d_in[9];
    const float* bg = (const float*)d_in[10];
    const float* wl = (const float*)d_in[11];
    const float* bl = (const float*)d_in[12];

    const int N = in_sizes[0] / 8;   // x is (N, 8)

    float* out = (float*)d_out;
    float* hn  = out + (size_t)N;
    float* cn  = hn + (size_t)N * 16;

    const int threads = 128;
    const int blocks  = 444;   // 3 resident blocks x 148 SMs, persistent
    gconvlstm_mma<<<blocks, threads>>>(x, h, c, Wx, bx, Wh, bh, wp, bg, wl, bl,
                                       out, hn, cn, N);
}